// round 14
// baseline (speedup 1.0000x reference)
#include <cuda_runtime.h>
#include <cuda_fp16.h>
#include <stdint.h>
#include <math.h>

// ---------------------------------------------------------------------------
// Problem constants
// ---------------------------------------------------------------------------
#define BB 256
#define TT 128
#define EE 300
#define HH 2048
#define GG 8192      // 4*H

#define KSEG_X 320   // phase-1 K (300 padded to 320)
#define LDA_XS (TT * KSEG_X)        // row stride (elements) between b and b+1 in g_xs

#define TILE_BYTES 16384            // 128 rows x 128 bytes (64 fp16), swizzled image
#define STAGE_BYTES (2 * TILE_BYTES)
#define SMEM_SZ (3 * STAGE_BYTES)   // 98304

#define NBLK_REC 128                // recurrence CTAs (64 x 2)
#define NBLK_ALL 148                // total CTAs (20 phase-1 workers)
#define NCHUNK 32                   // K chunks per recurrence step (2048/64)
#define NJOBS (TT * 128)            // phase-1 tiles: 128 slices x (2M x 64N)

// ---------------------------------------------------------------------------
// Device scratch (no allocations allowed)
// ---------------------------------------------------------------------------
__device__ __align__(16) __half  g_xg[(size_t)BB * TT * GG];    // fp16 gate-interleaved xg
// W_hh pre-tiled + pre-swizzled: [64 tileN][32 chunk][16384 B smem image]
__device__ __align__(16) unsigned char g_whh_t[(size_t)64 * NCHUNK * TILE_BYTES];
// h state pre-tiled + pre-swizzled, ping-pong: [2][2 tileM][32 chunk][16384 B]
__device__ __align__(16) unsigned char g_ht[2][(size_t)2 * NCHUNK * TILE_BYTES];
__device__ __align__(16) __half  g_wih[(size_t)GG * KSEG_X];    // plain fp16, rows reordered
__device__ __align__(16) __half  g_xs[(size_t)BB * TT * KSEG_X];// plain fp16 x, K padded
__device__ unsigned              g_bar_cnt;                     // recurrence step barrier
__device__ unsigned              g_p1_job;                      // phase-1 job counter
__device__ unsigned              g_tile_done[NJOBS];            // per-tile ready flags
__device__ float                 g_bias[GG];                     // reordered b_ih + b_hh

// ---------------------------------------------------------------------------
// PTX helpers (baseline ISA: cp.async(.bulk) / mbarrier / ldmatrix / mma.sync)
// ---------------------------------------------------------------------------
__device__ __forceinline__ uint32_t smem_u32(const void* p) {
    uint32_t a;
    asm("{ .reg .u64 t; cvta.to.shared.u64 t, %1; cvt.u32.u64 %0, t; }" : "=r"(a) : "l"(p));
    return a;
}

#define CP_ASYNC16(sa, ga) \
    asm volatile("cp.async.cg.shared.global [%0], [%1], 16;" :: "r"(sa), "l"(ga))
#define CP_COMMIT() asm volatile("cp.async.commit_group;")
#define CP_WAIT1()  asm volatile("cp.async.wait_group 1;")

#define MBAR_INIT(a, c) \
    asm volatile("mbarrier.init.shared.b64 [%0], %1;" :: "r"(a), "r"((uint32_t)(c)) : "memory")
#define MBAR_EXPECT_TX(a, bytes) \
    asm volatile("mbarrier.arrive.expect_tx.shared.b64 _, [%0], %1;" \
                 :: "r"(a), "r"((uint32_t)(bytes)) : "memory")
#define BULK_G2S(dst, src, bytes, mbar) \
    asm volatile("cp.async.bulk.shared::cluster.global.mbarrier::complete_tx::bytes " \
                 "[%0], [%1], %2, [%3];" \
                 :: "r"(dst), "l"(src), "r"((uint32_t)(bytes)), "r"(mbar) : "memory")

#define MBAR_WAIT(a, ph) do {                                                         \
    uint32_t _m = (a), _p = (uint32_t)(ph), _d;                                       \
    asm volatile("{ .reg .pred p; "                                                   \
        "mbarrier.try_wait.parity.acquire.cta.shared::cta.b64 p, [%1], %2; "          \
        "selp.b32 %0,1,0,p; }"                                                        \
        : "=r"(_d) : "r"(_m), "r"(_p) : "memory");                                    \
    if (!_d) {                                                                        \
        asm volatile("{ .reg .pred P1; "                                              \
            "WL_%=: mbarrier.try_wait.parity.acquire.cta.shared::cta.b64 P1, [%0], %1, 0x989680; " \
            "@P1 bra.uni WD_%=; bra.uni WL_%=; WD_%=: }"                              \
            :: "r"(_m), "r"(_p) : "memory");                                          \
    }                                                                                 \
} while (0)

#define LDSM_X4(r0, r1, r2, r3, addr) \
    asm volatile("ldmatrix.sync.aligned.m8n8.x4.shared.b16 {%0,%1,%2,%3}, [%4];" \
                 : "=r"(r0), "=r"(r1), "=r"(r2), "=r"(r3) : "r"(addr))

#define MMA_F16(d, a, b) \
    asm volatile("mma.sync.aligned.m16n8k16.row.col.f32.f16.f16.f32 " \
                 "{%0,%1,%2,%3}, {%4,%5,%6,%7}, {%8,%9}, {%0,%1,%2,%3};" \
                 : "+f"((d)[0]), "+f"((d)[1]), "+f"((d)[2]), "+f"((d)[3]) \
                 : "r"((a)[0]), "r"((a)[1]), "r"((a)[2]), "r"((a)[3]), \
                   "r"((b)[0]), "r"((b)[1]))

// Swizzled byte offset of element (row r 0..127, col kc 0..63) inside a tile image
__device__ __forceinline__ uint32_t tile_off(int r, int kc) {
    return (uint32_t)(r * 128 + ((((kc >> 3) ^ (r & 7))) << 4) + (kc & 7) * 2);
}

// ---------------------------------------------------------------------------
// GEMM compute (CTA tile 128x128, 8 warps = 4M x 2N, BK = 64)
// ---------------------------------------------------------------------------
struct Frag { float acc[2][8][4]; };

__device__ __forceinline__ void frag_zero(Frag& f) {
#pragma unroll
    for (int m = 0; m < 2; m++)
#pragma unroll
        for (int n = 0; n < 8; n++)
#pragma unroll
            for (int v = 0; v < 4; v++) f.acc[m][n][v] = 0.0f;
}

__device__ __forceinline__ void compute_chunk(uint32_t sb, int lane, int wm, int wn,
                                              Frag& f) {
    const uint32_t aB = sb;
    const uint32_t bB = sb + TILE_BYTES;
#pragma unroll
    for (int k16 = 0; k16 < 4; k16++) {
        const int kb = k16 * 2 + (lane >> 4);
        uint32_t a1[2][4];
#pragma unroll
        for (int m = 0; m < 2; m++) {
            const int r = wm * 32 + m * 16 + (lane & 15);
            const uint32_t off = r * 128 + ((kb ^ (r & 7)) << 4);
            LDSM_X4(a1[m][0], a1[m][1], a1[m][2], a1[m][3], aB + off);
        }
        uint32_t bf[8][2];
#pragma unroll
        for (int np = 0; np < 4; np++) {
            const int r = wn * 64 + np * 16 + (lane & 15);
            const uint32_t off = r * 128 + ((kb ^ (r & 7)) << 4);
            uint32_t t0, t1, t2, t3;
            LDSM_X4(t0, t1, t2, t3, bB + off);
            bf[np*2][0] = t0; bf[np*2][1] = t2;
            bf[np*2+1][0] = t1; bf[np*2+1][1] = t3;
        }
#pragma unroll
        for (int m = 0; m < 2; m++)
#pragma unroll
            for (int n = 0; n < 8; n++)
                MMA_F16(f.acc[m][n], a1[m], bf[n]);
    }
}

// ---------------------------------------------------------------------------
// Fused persistent kernel: 148 CTAs.
//  CTA 0..127  : LSTM recurrence (tileN = bx & 63, tileM = bx >> 6)
//  CTA 128..147: phase-1 workers producing xg tiles in t-major order
// ---------------------------------------------------------------------------
__global__ void __launch_bounds__(256, 1)
lstm_fused_kernel(float* __restrict__ out)
{
    extern __shared__ char smem[];
    __shared__ __align__(8) unsigned long long mbar[3];
    __shared__ int sh_job;

    const int tid  = threadIdx.x;
    const int lane = tid & 31;
    const int wid  = tid >> 5;
    const int wm   = wid >> 1;
    const int wn   = wid & 1;
    const int bx   = blockIdx.x;
    const uint32_t sbase = smem_u32(smem);

    if (bx < NBLK_REC) {
        // =================== RECURRENCE ROLE ===================
        const int tileN = bx & 63;
        const int tileM = bx >> 6;
        uint32_t mb[3];
#pragma unroll
        for (int s = 0; s < 3; s++) mb[s] = smem_u32(&mbar[s]);
        if (tid == 0) { MBAR_INIT(mb[0], 1); MBAR_INIT(mb[1], 1); MBAR_INIT(mb[2], 1); }
        __syncthreads();

        const unsigned char* bTiles = g_whh_t + (size_t)tileN * NCHUNK * TILE_BYTES;
        int ph[3] = {0, 0, 0};

        float c_reg[2][8];
#pragma unroll
        for (int m = 0; m < 2; m++)
#pragma unroll
            for (int n = 0; n < 8; n++) c_reg[m][n] = 0.0f;

        const int odd = lane & 1;

        for (int t = 0; t < TT; t++) {
            Frag f;
            frag_zero(f);

            if (t > 0) {    // t==0: h=0, GEMM contributes nothing
                const unsigned char* aTiles =
                    g_ht[t & 1] + (size_t)tileM * NCHUNK * TILE_BYTES;
                auto issue = [&](int it) {
                    if (tid == 0 && it < NCHUNK) {
                        const int s = it % 3;
                        const uint32_t sb = sbase + s * STAGE_BYTES;
                        MBAR_EXPECT_TX(mb[s], STAGE_BYTES);
                        BULK_G2S(sb,              aTiles + (size_t)it * TILE_BYTES, TILE_BYTES, mb[s]);
                        BULK_G2S(sb + TILE_BYTES, bTiles + (size_t)it * TILE_BYTES, TILE_BYTES, mb[s]);
                    }
                };
                issue(0); issue(1);
                for (int it = 0; it < NCHUNK; it++) {
                    const int s = it % 3;
                    MBAR_WAIT(mb[s], ph[s] & 1);
                    ph[s]++;
                    __syncthreads();
                    issue(it + 2);
                    compute_chunk(sbase + s * STAGE_BYTES, lane, wm, wn, f);
                }
            }

            // ---- wait for xg tile (t, tileM, tileN) from phase-1 workers ----
            {
                if (tid == 0) {
                    volatile unsigned* flag =
                        &g_tile_done[t * 128 + tileM * 64 + tileN];
                    while (*flag == 0u) { }
                }
                __syncthreads();
                __threadfence();
            }

            // ---- fused LSTM cell epilogue ----
            const int nxt = (t & 1) ^ 1;
            unsigned char* hOut = g_ht[nxt];
#pragma unroll
            for (int m = 0; m < 2; m++) {
#pragma unroll
                for (int n = 0; n < 8; n++) {
                    const float c0 = f.acc[m][n][0], c1 = f.acc[m][n][1];
                    const float c2 = f.acc[m][n][2], c3 = f.acc[m][n][3];
                    const float s0 = odd ? c0 : c2;
                    const float s1 = odd ? c1 : c3;
                    const float rx = __shfl_xor_sync(0xffffffffu, s0, 1);
                    const float ry = __shfl_xor_sync(0xffffffffu, s1, 1);
                    const float gi = odd ? rx : c0;
                    const float gf = odd ? ry : c1;
                    const float gg = odd ? c2 : rx;
                    const float go = odd ? c3 : ry;
                    const int b  = tileM * 128 + wm * 32 + m * 16 + (lane >> 2) + (odd ? 8 : 0);
                    const int ug = tileN * 32 + wn * 16 + n * 2 + ((lane & 3) >> 1);

                    const uint2 xw = *(const uint2*)(g_xg + ((size_t)b * TT + t) * GG + 4 * (size_t)ug);
                    const float2 x01 = __half22float2(*(const __half2*)&xw.x);
                    const float2 x23 = __half22float2(*(const __half2*)&xw.y);
                    const float pi = gi + x01.x;
                    const float pf = gf + x01.y;
                    const float pg = gg + x23.x;
                    const float po = go + x23.y;

                    const float ig = 1.0f / (1.0f + __expf(-pi));
                    const float fg = 1.0f / (1.0f + __expf(-pf));
                    const float eg = __expf(-2.0f * fabsf(pg));
                    const float tg = copysignf((1.0f - eg) / (1.0f + eg), pg);
                    const float og = 1.0f / (1.0f + __expf(-po));

                    const float cn = fg * c_reg[m][n] + ig * tg;
                    c_reg[m][n] = cn;
                    const float ec = __expf(-2.0f * fabsf(cn));
                    const float th = copysignf((1.0f - ec) / (1.0f + ec), cn);
                    const float h  = og * th;

                    const size_t hoff = ((size_t)(b >> 7) * NCHUNK + (ug >> 6)) * TILE_BYTES
                                      + tile_off(b & 127, ug & 63);
                    *(__half*)(hOut + hoff) = __float2half(h);
                    if (t == TT - 1) out[(size_t)b * HH + ug] = h;
                }
            }

            // ---- global step barrier (128 recurrence CTAs) ----
            __syncthreads();
            if (tid == 0) {
                __threadfence();
                atomicAdd(&g_bar_cnt, 1u);
                const unsigned target = (unsigned)(t + 1) * NBLK_REC;
                while (*(volatile unsigned*)&g_bar_cnt < target) { }
                __threadfence();
            }
            __syncthreads();
        }
    } else {
        // =================== PHASE-1 WORKER ROLE ===================
        // xg tile job j: t = j>>7, tM = (j>>6)&1, tN = j&63.
        // Tile: rows b in [tM*128,+128), cols [tN*128,+128), K = 320.
        uint32_t soff[4];
        int rr[4], kk[4];
#pragma unroll
        for (int s = 0; s < 4; s++) {
            const int linear = tid + s * 256;
            rr[s] = linear >> 3;
            kk[s] = (linear & 7) * 8;
            soff[s] = rr[s] * 128 + (((linear & 7) ^ (rr[s] & 7)) << 4);
        }

        for (;;) {
            if (tid == 0) sh_job = (int)atomicAdd(&g_p1_job, 1u);
            __syncthreads();
            const int j = sh_job;
            if (j >= NJOBS) break;
            const int t  = j >> 7;
            const int tM = (j >> 6) & 1;
            const int tN = j & 63;

            const __half* aBase = g_xs + (size_t)(tM * 128) * LDA_XS + (size_t)t * KSEG_X;
            const __half* bBase = g_wih + (size_t)(tN * 128) * KSEG_X;

            Frag f;
            frag_zero(f);

            const int niter = KSEG_X / 64;   // 5
            auto issue = [&](int it) {
                if (it < niter) {
                    const int k0 = it * 64;
                    const uint32_t sb = sbase + (it % 3) * STAGE_BYTES;
#pragma unroll
                    for (int s = 0; s < 4; s++)
                        CP_ASYNC16(sb + soff[s],
                                   aBase + (size_t)rr[s] * LDA_XS + k0 + kk[s]);
#pragma unroll
                    for (int s = 0; s < 4; s++)
                        CP_ASYNC16(sb + TILE_BYTES + soff[s],
                                   bBase + (size_t)rr[s] * KSEG_X + k0 + kk[s]);
                }
                CP_COMMIT();
            };

            issue(0); issue(1);
            for (int it = 0; it < niter; it++) {
                CP_WAIT1();
                __syncthreads();
                issue(it + 2);
                compute_chunk(sbase + (it % 3) * STAGE_BYTES, lane, wm, wn, f);
            }

            // Epilogue: fp16 xg with bias; row b -> g_xg[(b*TT + t)*GG + col]
#pragma unroll
            for (int m = 0; m < 2; m++) {
                const int b0 = tM * 128 + wm * 32 + m * 16 + (lane >> 2);
#pragma unroll
                for (int n = 0; n < 8; n++) {
                    const int col = tN * 128 + wn * 64 + n * 8 + 2 * (lane & 3);
                    const float2 bz = *(const float2*)(g_bias + col);
                    const __half2 v0 = __floats2half2_rn(f.acc[m][n][0] + bz.x,
                                                         f.acc[m][n][1] + bz.y);
                    const __half2 v1 = __floats2half2_rn(f.acc[m][n][2] + bz.x,
                                                         f.acc[m][n][3] + bz.y);
                    *(__half2*)(g_xg + ((size_t)b0 * TT + t) * GG + col)       = v0;
                    *(__half2*)(g_xg + ((size_t)(b0 + 8) * TT + t) * GG + col) = v1;
                }
            }

            __syncthreads();
            if (tid == 0) {
                __threadfence();
                atomicExch(&g_tile_done[j], 1u);
            }
            __syncthreads();
        }
    }
}

// ---------------------------------------------------------------------------
// Prep kernels.  Reordered row r  <->  original row (r&3)*H + (r>>2).
// ---------------------------------------------------------------------------
__global__ void prep_whh_kernel(const float* __restrict__ W) {
    int idx = blockIdx.x * blockDim.x + threadIdx.x;
    if (idx >= GG * HH) return;
    int rg = idx / HH, k = idx - rg * HH;
    int orig = (rg & 3) * HH + (rg >> 2);
    const float w = W[(size_t)orig * HH + k];
    const size_t off = ((size_t)(rg >> 7) * NCHUNK + (k >> 6)) * TILE_BYTES
                     + tile_off(rg & 127, k & 63);
    *(__half*)(g_whh_t + off) = __float2half(w);
}

__global__ void prep_wih_kernel(const float* __restrict__ W) {
    int idx = blockIdx.x * blockDim.x + threadIdx.x;
    if (idx >= GG * KSEG_X) return;
    int r = idx / KSEG_X, k = idx - r * KSEG_X;
    int orig = (r & 3) * HH + (r >> 2);
    float w = (k < EE) ? W[(size_t)orig * EE + k] : 0.0f;
    g_wih[(size_t)r * KSEG_X + k] = __float2half(w);
}

__global__ void prep_x_kernel(const float* __restrict__ x) {
    int idx = blockIdx.x * blockDim.x + threadIdx.x;
    if (idx >= BB * TT * KSEG_X) return;
    int m = idx / KSEG_X, k = idx - m * KSEG_X;
    g_xs[(size_t)m * KSEG_X + k] = __float2half((k < EE) ? x[(size_t)m * EE + k] : 0.0f);
}

__global__ void prep_bias_kernel(const float* __restrict__ b_ih,
                                 const float* __restrict__ b_hh) {
    int n = blockIdx.x * blockDim.x + threadIdx.x;
    if (n >= GG) return;
    int orig = (n & 3) * HH + (n >> 2);
    g_bias[n] = b_ih[orig] + b_hh[orig];
}

__global__ void init_state_kernel() {
    int i = blockIdx.x * blockDim.x + threadIdx.x;
    if (i == 0) { g_bar_cnt = 0; g_p1_job = 0; }
    if (i < NJOBS) g_tile_done[i] = 0u;
}

// ---------------------------------------------------------------------------
// Launch
// ---------------------------------------------------------------------------
extern "C" void kernel_launch(void* const* d_in, const int* in_sizes, int n_in,
                              void* d_out, int out_size) {
    const float* x    = (const float*)d_in[0];   // [B, T, E]
    const float* W_ih = (const float*)d_in[1];   // [4H, E]
    const float* W_hh = (const float*)d_in[2];   // [4H, H]
    const float* b_ih = (const float*)d_in[3];   // [4H]
    const float* b_hh = (const float*)d_in[4];   // [4H]
    float* out = (float*)d_out;                  // [B, H]

    cudaFuncSetAttribute(lstm_fused_kernel,
                         cudaFuncAttributeMaxDynamicSharedMemorySize, SMEM_SZ);

    // Prep
    prep_whh_kernel<<<(GG * HH + 255) / 256, 256>>>(W_hh);
    prep_wih_kernel<<<(GG * KSEG_X + 255) / 256, 256>>>(W_ih);
    prep_x_kernel<<<(BB * TT * KSEG_X + 255) / 256, 256>>>(x);
    prep_bias_kernel<<<(GG + 255) / 256, 256>>>(b_ih, b_hh);
    init_state_kernel<<<(NJOBS + 255) / 256, 256>>>();

    // Fused persistent kernel: phase-1 producers + LSTM recurrence consumers
    lstm_fused_kernel<<<NBLK_ALL, 256, SMEM_SZ>>>(out);
}

// round 15
// speedup vs baseline: 1.3229x; 1.3229x over previous
#include <cuda_runtime.h>
#include <cuda_fp16.h>
#include <stdint.h>
#include <math.h>

// ---------------------------------------------------------------------------
// Problem constants
// ---------------------------------------------------------------------------
#define BB 256
#define TT 128
#define EE 300
#define HH 2048
#define GG 8192      // 4*H

#define KSEG_X 320   // phase-1 K (300 padded to 320)
#define LDA_XS (TT * KSEG_X)        // element stride between b and b+1 in g_xs

#define TILE_BYTES 16384            // 128 rows x 128 bytes (64 fp16), swizzled image
#define STAGE_BYTES (2 * TILE_BYTES)
#define SMEM_SZ (3 * STAGE_BYTES)   // 98304

#define NBLK_REC 128                // recurrence CTAs (64 N x 2 M)
#define NBLK_ALL 148                // total CTAs (20 phase-1 producers)
#define NCHUNK 32                   // K chunks per recurrence step (2048/64)

#define T0 64                       // slices t<T0 computed by serial prelude
#define NJOBS_P ((TT - T0) * 128)   // producer jobs (t>=T0)

// ---------------------------------------------------------------------------
// Device scratch (no allocations allowed)
// ---------------------------------------------------------------------------
__device__ __align__(16) __half  g_xg[(size_t)BB * TT * GG];    // fp16 gate-interleaved xg
__device__ __align__(16) unsigned char g_whh_t[(size_t)64 * NCHUNK * TILE_BYTES];
__device__ __align__(16) unsigned char g_ht[2][(size_t)2 * NCHUNK * TILE_BYTES];
__device__ __align__(16) __half  g_wih[(size_t)GG * KSEG_X];    // plain fp16, rows reordered
__device__ __align__(16) __half  g_xs[(size_t)BB * TT * KSEG_X];// plain fp16 x, K padded
__device__ unsigned              g_bar_cnt;                     // recurrence step barrier
__device__ unsigned              g_p1_job;                      // producer job counter
__device__ unsigned              g_tile_done[TT * 128];         // flags (used for t>=T0)
__device__ float                 g_bias[GG];                     // reordered b_ih + b_hh

// ---------------------------------------------------------------------------
// PTX helpers (baseline ISA: cp.async(.bulk) / mbarrier / ldmatrix / mma.sync)
// ---------------------------------------------------------------------------
__device__ __forceinline__ uint32_t smem_u32(const void* p) {
    uint32_t a;
    asm("{ .reg .u64 t; cvta.to.shared.u64 t, %1; cvt.u32.u64 %0, t; }" : "=r"(a) : "l"(p));
    return a;
}

#define CP_ASYNC16(sa, ga) \
    asm volatile("cp.async.cg.shared.global [%0], [%1], 16;" :: "r"(sa), "l"(ga))
#define CP_COMMIT() asm volatile("cp.async.commit_group;")
#define CP_WAIT1()  asm volatile("cp.async.wait_group 1;")

#define MBAR_INIT(a, c) \
    asm volatile("mbarrier.init.shared.b64 [%0], %1;" :: "r"(a), "r"((uint32_t)(c)) : "memory")
#define MBAR_EXPECT_TX(a, bytes) \
    asm volatile("mbarrier.arrive.expect_tx.shared.b64 _, [%0], %1;" \
                 :: "r"(a), "r"((uint32_t)(bytes)) : "memory")
#define BULK_G2S(dst, src, bytes, mbar) \
    asm volatile("cp.async.bulk.shared::cluster.global.mbarrier::complete_tx::bytes " \
                 "[%0], [%1], %2, [%3];" \
                 :: "r"(dst), "l"(src), "r"((uint32_t)(bytes)), "r"(mbar) : "memory")

#define MBAR_WAIT(a, ph) do {                                                         \
    uint32_t _m = (a), _p = (uint32_t)(ph), _d;                                       \
    asm volatile("{ .reg .pred p; "                                                   \
        "mbarrier.try_wait.parity.acquire.cta.shared::cta.b64 p, [%1], %2; "          \
        "selp.b32 %0,1,0,p; }"                                                        \
        : "=r"(_d) : "r"(_m), "r"(_p) : "memory");                                    \
    if (!_d) {                                                                        \
        asm volatile("{ .reg .pred P1; "                                              \
            "WL_%=: mbarrier.try_wait.parity.acquire.cta.shared::cta.b64 P1, [%0], %1, 0x989680; " \
            "@P1 bra.uni WD_%=; bra.uni WL_%=; WD_%=: }"                              \
            :: "r"(_m), "r"(_p) : "memory");                                          \
    }                                                                                 \
} while (0)

#define LDSM_X4(r0, r1, r2, r3, addr) \
    asm volatile("ldmatrix.sync.aligned.m8n8.x4.shared.b16 {%0,%1,%2,%3}, [%4];" \
                 : "=r"(r0), "=r"(r1), "=r"(r2), "=r"(r3) : "r"(addr))

#define MMA_F16(d, a, b) \
    asm volatile("mma.sync.aligned.m16n8k16.row.col.f32.f16.f16.f32 " \
                 "{%0,%1,%2,%3}, {%4,%5,%6,%7}, {%8,%9}, {%0,%1,%2,%3};" \
                 : "+f"((d)[0]), "+f"((d)[1]), "+f"((d)[2]), "+f"((d)[3]) \
                 : "r"((a)[0]), "r"((a)[1]), "r"((a)[2]), "r"((a)[3]), \
                   "r"((b)[0]), "r"((b)[1]))

// Swizzled byte offset of element (row r 0..127, col kc 0..63) inside a tile image
__device__ __forceinline__ uint32_t tile_off(int r, int kc) {
    return (uint32_t)(r * 128 + ((((kc >> 3) ^ (r & 7))) << 4) + (kc & 7) * 2);
}

// ---------------------------------------------------------------------------
// GEMM compute (CTA tile 128x128, 8 warps = 4M x 2N, BK = 64)
// ---------------------------------------------------------------------------
struct Frag { float acc[2][8][4]; };

__device__ __forceinline__ void frag_zero(Frag& f) {
#pragma unroll
    for (int m = 0; m < 2; m++)
#pragma unroll
        for (int n = 0; n < 8; n++)
#pragma unroll
            for (int v = 0; v < 4; v++) f.acc[m][n][v] = 0.0f;
}

__device__ __forceinline__ void compute_chunk(uint32_t sb, int lane, int wm, int wn,
                                              Frag& f) {
    const uint32_t aB = sb;
    const uint32_t bB = sb + TILE_BYTES;
#pragma unroll
    for (int k16 = 0; k16 < 4; k16++) {
        const int kb = k16 * 2 + (lane >> 4);
        uint32_t a1[2][4];
#pragma unroll
        for (int m = 0; m < 2; m++) {
            const int r = wm * 32 + m * 16 + (lane & 15);
            const uint32_t off = r * 128 + ((kb ^ (r & 7)) << 4);
            LDSM_X4(a1[m][0], a1[m][1], a1[m][2], a1[m][3], aB + off);
        }
        uint32_t bf[8][2];
#pragma unroll
        for (int np = 0; np < 4; np++) {
            const int r = wn * 64 + np * 16 + (lane & 15);
            const uint32_t off = r * 128 + ((kb ^ (r & 7)) << 4);
            uint32_t t0, t1, t2, t3;
            LDSM_X4(t0, t1, t2, t3, bB + off);
            bf[np*2][0] = t0; bf[np*2][1] = t2;
            bf[np*2+1][0] = t1; bf[np*2+1][1] = t3;
        }
#pragma unroll
        for (int m = 0; m < 2; m++)
#pragma unroll
            for (int n = 0; n < 8; n++)
                MMA_F16(f.acc[m][n], a1[m], bf[n]);
    }
}

// ---------------------------------------------------------------------------
// Phase-1 tile worker: xg tile (t, tM, tN) += bias  (LDGSTS 3-stage pipeline)
// ---------------------------------------------------------------------------
__device__ __forceinline__ void p1_tile(int t, int tM, int tN,
                                        uint32_t sbase, int tid, int lane,
                                        int wm, int wn) {
    uint32_t soff[4];
    int rr[4], kk[4];
#pragma unroll
    for (int s = 0; s < 4; s++) {
        const int linear = tid + s * 256;
        rr[s] = linear >> 3;
        kk[s] = (linear & 7) * 8;
        soff[s] = rr[s] * 128 + (((linear & 7) ^ (rr[s] & 7)) << 4);
    }
    const __half* aBase = g_xs + (size_t)(tM * 128) * LDA_XS + (size_t)t * KSEG_X;
    const __half* bBase = g_wih + (size_t)(tN * 128) * KSEG_X;

    Frag f;
    frag_zero(f);

    const int niter = KSEG_X / 64;   // 5
    auto issue = [&](int it) {
        if (it < niter) {
            const int k0 = it * 64;
            const uint32_t sb = sbase + (it % 3) * STAGE_BYTES;
#pragma unroll
            for (int s = 0; s < 4; s++)
                CP_ASYNC16(sb + soff[s], aBase + (size_t)rr[s] * LDA_XS + k0 + kk[s]);
#pragma unroll
            for (int s = 0; s < 4; s++)
                CP_ASYNC16(sb + TILE_BYTES + soff[s], bBase + (size_t)rr[s] * KSEG_X + k0 + kk[s]);
        }
        CP_COMMIT();
    };

    issue(0); issue(1);
    for (int it = 0; it < niter; it++) {
        CP_WAIT1();
        __syncthreads();
        issue(it + 2);
        compute_chunk(sbase + (it % 3) * STAGE_BYTES, lane, wm, wn, f);
    }

#pragma unroll
    for (int m = 0; m < 2; m++) {
        const int b0 = tM * 128 + wm * 32 + m * 16 + (lane >> 2);
#pragma unroll
        for (int n = 0; n < 8; n++) {
            const int col = tN * 128 + wn * 64 + n * 8 + 2 * (lane & 3);
            const float2 bz = *(const float2*)(g_bias + col);
            const __half2 v0 = __floats2half2_rn(f.acc[m][n][0] + bz.x,
                                                 f.acc[m][n][1] + bz.y);
            const __half2 v1 = __floats2half2_rn(f.acc[m][n][2] + bz.x,
                                                 f.acc[m][n][3] + bz.y);
            *(__half2*)(g_xg + ((size_t)b0 * TT + t) * GG + col)       = v0;
            *(__half2*)(g_xg + ((size_t)(b0 + 8) * TT + t) * GG + col) = v1;
        }
    }
}

// ---------------------------------------------------------------------------
// Serial phase-1 prelude: all xg slices t < T0 (full-chip)
// grid (64, 2*T0): tN = bx, t = by>>1, tM = by&1
// ---------------------------------------------------------------------------
__global__ void __launch_bounds__(256, 1)
p1_prelude_kernel() {
    extern __shared__ char smem[];
    const int tid  = threadIdx.x;
    p1_tile(blockIdx.y >> 1, blockIdx.y & 1, blockIdx.x,
            smem_u32(smem), tid, tid & 31, (tid >> 5) >> 1, (tid >> 5) & 1);
}

// ---------------------------------------------------------------------------
// Fused persistent kernel: 148 CTAs.
//  CTA 0..127  : LSTM recurrence (tileN = bx & 63, tileM = bx >> 6)
//  CTA 128..147: producers for xg slices t >= T0 (t-major job order)
// ---------------------------------------------------------------------------
__global__ void __launch_bounds__(256, 1)
lstm_fused_kernel(float* __restrict__ out)
{
    extern __shared__ char smem[];
    __shared__ __align__(8) unsigned long long mbar[3];
    __shared__ int sh_job;

    const int tid  = threadIdx.x;
    const int lane = tid & 31;
    const int wid  = tid >> 5;
    const int wm   = wid >> 1;
    const int wn   = wid & 1;
    const int bx   = blockIdx.x;
    const uint32_t sbase = smem_u32(smem);

    if (bx < NBLK_REC) {
        // =================== RECURRENCE ROLE ===================
        const int tileN = bx & 63;
        const int tileM = bx >> 6;
        uint32_t mb[3];
#pragma unroll
        for (int s = 0; s < 3; s++) mb[s] = smem_u32(&mbar[s]);
        if (tid == 0) { MBAR_INIT(mb[0], 1); MBAR_INIT(mb[1], 1); MBAR_INIT(mb[2], 1); }
        __syncthreads();

        const unsigned char* bTiles = g_whh_t + (size_t)tileN * NCHUNK * TILE_BYTES;
        int ph[3] = {0, 0, 0};

        float c_reg[2][8];
#pragma unroll
        for (int m = 0; m < 2; m++)
#pragma unroll
            for (int n = 0; n < 8; n++) c_reg[m][n] = 0.0f;

        const int odd = lane & 1;

        for (int t = 0; t < TT; t++) {
            Frag f;
            frag_zero(f);

            if (t > 0) {    // t==0: h=0, GEMM contributes nothing
                const unsigned char* aTiles =
                    g_ht[t & 1] + (size_t)tileM * NCHUNK * TILE_BYTES;
                auto issue = [&](int it) {
                    if (tid == 0 && it < NCHUNK) {
                        const int s = it % 3;
                        const uint32_t sb = sbase + s * STAGE_BYTES;
                        MBAR_EXPECT_TX(mb[s], STAGE_BYTES);
                        BULK_G2S(sb,              aTiles + (size_t)it * TILE_BYTES, TILE_BYTES, mb[s]);
                        BULK_G2S(sb + TILE_BYTES, bTiles + (size_t)it * TILE_BYTES, TILE_BYTES, mb[s]);
                    }
                };
                issue(0); issue(1);
                for (int it = 0; it < NCHUNK; it++) {
                    const int s = it % 3;
                    MBAR_WAIT(mb[s], ph[s] & 1);
                    ph[s]++;
                    __syncthreads();
                    issue(it + 2);
                    compute_chunk(sbase + s * STAGE_BYTES, lane, wm, wn, f);
                }
            }

            // ---- wait for producer xg tile only in the overlapped region ----
            if (t >= T0) {
                if (tid == 0) {
                    volatile unsigned* flag =
                        &g_tile_done[t * 128 + tileM * 64 + tileN];
                    while (*flag == 0u) { }
                }
                __syncthreads();
                __threadfence();
            }

            // ---- fused LSTM cell epilogue ----
            const int nxt = (t & 1) ^ 1;
            unsigned char* hOut = g_ht[nxt];
#pragma unroll
            for (int m = 0; m < 2; m++) {
#pragma unroll
                for (int n = 0; n < 8; n++) {
                    const float c0 = f.acc[m][n][0], c1 = f.acc[m][n][1];
                    const float c2 = f.acc[m][n][2], c3 = f.acc[m][n][3];
                    const float s0 = odd ? c0 : c2;
                    const float s1 = odd ? c1 : c3;
                    const float rx = __shfl_xor_sync(0xffffffffu, s0, 1);
                    const float ry = __shfl_xor_sync(0xffffffffu, s1, 1);
                    const float gi = odd ? rx : c0;
                    const float gf = odd ? ry : c1;
                    const float gg = odd ? c2 : rx;
                    const float go = odd ? c3 : ry;
                    const int b  = tileM * 128 + wm * 32 + m * 16 + (lane >> 2) + (odd ? 8 : 0);
                    const int ug = tileN * 32 + wn * 16 + n * 2 + ((lane & 3) >> 1);

                    const uint2 xw = *(const uint2*)(g_xg + ((size_t)b * TT + t) * GG + 4 * (size_t)ug);
                    const float2 x01 = __half22float2(*(const __half2*)&xw.x);
                    const float2 x23 = __half22float2(*(const __half2*)&xw.y);
                    const float pi = gi + x01.x;
                    const float pf = gf + x01.y;
                    const float pg = gg + x23.x;
                    const float po = go + x23.y;

                    const float ig = 1.0f / (1.0f + __expf(-pi));
                    const float fg = 1.0f / (1.0f + __expf(-pf));
                    const float eg = __expf(-2.0f * fabsf(pg));
                    const float tg = copysignf((1.0f - eg) / (1.0f + eg), pg);
                    const float og = 1.0f / (1.0f + __expf(-po));

                    const float cn = fg * c_reg[m][n] + ig * tg;
                    c_reg[m][n] = cn;
                    const float ec = __expf(-2.0f * fabsf(cn));
                    const float th = copysignf((1.0f - ec) / (1.0f + ec), cn);
                    const float h  = og * th;

                    const size_t hoff = ((size_t)(b >> 7) * NCHUNK + (ug >> 6)) * TILE_BYTES
                                      + tile_off(b & 127, ug & 63);
                    *(__half*)(hOut + hoff) = __float2half(h);
                    if (t == TT - 1) out[(size_t)b * HH + ug] = h;
                }
            }

            // ---- global step barrier (128 recurrence CTAs) ----
            __syncthreads();
            if (tid == 0) {
                __threadfence();
                atomicAdd(&g_bar_cnt, 1u);
                const unsigned target = (unsigned)(t + 1) * NBLK_REC;
                while (*(volatile unsigned*)&g_bar_cnt < target) { }
                __threadfence();
            }
            __syncthreads();
        }
    } else {
        // =================== PRODUCER ROLE (t >= T0) ===================
        for (;;) {
            if (tid == 0) sh_job = (int)atomicAdd(&g_p1_job, 1u);
            __syncthreads();
            const int j = sh_job;
            if (j >= NJOBS_P) break;
            const int t  = T0 + (j >> 7);
            const int tM = (j >> 6) & 1;
            const int tN = j & 63;

            p1_tile(t, tM, tN, sbase, tid, lane, wm, wn);

            __syncthreads();
            if (tid == 0) {
                __threadfence();
                atomicExch(&g_tile_done[t * 128 + tM * 64 + tN], 1u);
            }
            __syncthreads();
        }
    }
}

// ---------------------------------------------------------------------------
// Prep kernels.  Reordered row r  <->  original row (r&3)*H + (r>>2).
// ---------------------------------------------------------------------------
__global__ void prep_whh_kernel(const float* __restrict__ W) {
    int idx = blockIdx.x * blockDim.x + threadIdx.x;
    if (idx >= GG * HH) return;
    int rg = idx / HH, k = idx - rg * HH;
    int orig = (rg & 3) * HH + (rg >> 2);
    const float w = W[(size_t)orig * HH + k];
    const size_t off = ((size_t)(rg >> 7) * NCHUNK + (k >> 6)) * TILE_BYTES
                     + tile_off(rg & 127, k & 63);
    *(__half*)(g_whh_t + off) = __float2half(w);
}

__global__ void prep_wih_kernel(const float* __restrict__ W) {
    int idx = blockIdx.x * blockDim.x + threadIdx.x;
    if (idx >= GG * KSEG_X) return;
    int r = idx / KSEG_X, k = idx - r * KSEG_X;
    int orig = (r & 3) * HH + (r >> 2);
    float w = (k < EE) ? W[(size_t)orig * EE + k] : 0.0f;
    g_wih[(size_t)r * KSEG_X + k] = __float2half(w);
}

__global__ void prep_x_kernel(const float* __restrict__ x) {
    int idx = blockIdx.x * blockDim.x + threadIdx.x;
    if (idx >= BB * TT * KSEG_X) return;
    int m = idx / KSEG_X, k = idx - m * KSEG_X;
    g_xs[(size_t)m * KSEG_X + k] = __float2half((k < EE) ? x[(size_t)m * EE + k] : 0.0f);
}

__global__ void prep_bias_kernel(const float* __restrict__ b_ih,
                                 const float* __restrict__ b_hh) {
    int n = blockIdx.x * blockDim.x + threadIdx.x;
    if (n >= GG) return;
    int orig = (n & 3) * HH + (n >> 2);
    g_bias[n] = b_ih[orig] + b_hh[orig];
}

__global__ void init_state_kernel() {
    int i = blockIdx.x * blockDim.x + threadIdx.x;
    if (i == 0) { g_bar_cnt = 0; g_p1_job = 0; }
    if (i < TT * 128) g_tile_done[i] = 0u;
}

// ---------------------------------------------------------------------------
// Launch
// ---------------------------------------------------------------------------
extern "C" void kernel_launch(void* const* d_in, const int* in_sizes, int n_in,
                              void* d_out, int out_size) {
    const float* x    = (const float*)d_in[0];   // [B, T, E]
    const float* W_ih = (const float*)d_in[1];   // [4H, E]
    const float* W_hh = (const float*)d_in[2];   // [4H, H]
    const float* b_ih = (const float*)d_in[3];   // [4H]
    const float* b_hh = (const float*)d_in[4];   // [4H]
    float* out = (float*)d_out;                  // [B, H]

    cudaFuncSetAttribute(p1_prelude_kernel,
                         cudaFuncAttributeMaxDynamicSharedMemorySize, SMEM_SZ);
    cudaFuncSetAttribute(lstm_fused_kernel,
                         cudaFuncAttributeMaxDynamicSharedMemorySize, SMEM_SZ);

    // Prep
    prep_whh_kernel<<<(GG * HH + 255) / 256, 256>>>(W_hh);
    prep_wih_kernel<<<(GG * KSEG_X + 255) / 256, 256>>>(W_ih);
    prep_x_kernel<<<(BB * TT * KSEG_X + 255) / 256, 256>>>(x);
    prep_bias_kernel<<<(GG + 255) / 256, 256>>>(b_ih, b_hh);
    init_state_kernel<<<(TT * 128 + 255) / 256, 256>>>();

    // Serial phase-1 prelude: slices t < T0, full-chip
    {
        dim3 grid(64, 2 * T0);
        p1_prelude_kernel<<<grid, 256, SMEM_SZ>>>();
    }

    // Fused persistent kernel: recurrence + producers for t >= T0
    lstm_fused_kernel<<<NBLK_ALL, 256, SMEM_SZ>>>(out);
}